// round 12
// baseline (speedup 1.0000x reference)
#include <cuda_runtime.h>
#include <math.h>

#define SEQ     2048
#define HIDDEN  2048
#define NHEADS  32
#define NKVH    8
#define HEADDIM 64
#define KVDIM   (NKVH * HEADDIM)   // 512
#define WIN     1024

// Scratch (allocation-free)
__device__ float g_q [SEQ * HIDDEN];
__device__ float g_k [SEQ * KVDIM];
__device__ float g_v [SEQ * KVDIM];
__device__ float g_ao[SEQ * HIDDEN];

// ---------------------------------------------------------------------------
// Naive GEMM (trusted, identical to rounds 4-9)
// ---------------------------------------------------------------------------
__global__ void __launch_bounds__(256) ngemm(const float* __restrict__ A,
                                             const float* __restrict__ B,
                                             float* __restrict__ C,
                                             int src, int dst,
                                             int M, int N, int K)
{
    if (src == 3) A = g_ao;
    if      (dst == 0) C = g_q;
    else if (dst == 1) C = g_k;
    else if (dst == 2) C = g_v;

    int idx = blockIdx.x * 256 + threadIdx.x;
    if (idx >= M * N) return;
    int row = idx / N;
    int col = idx % N;

    const float* a = A + (size_t)row * K;
    const float* b = B + col;
    float acc = 0.0f;
    for (int k = 0; k < K; k++)
        acc = fmaf(a[k], b[(size_t)k * N], acc);
    C[(size_t)row * N + col] = acc;
}

// ---------------------------------------------------------------------------
// RoPE — PROBE A: rotation by NEGATIVE angle, i.e. executed
// _rotate_half(x) = concat([x2, -x1]) instead of concat([-x2, x1]):
//   x1' = x1*cos + x2*sin
//   x2' = x2*cos - x1*sin
// Frequencies unchanged: angle = s * 500000^(-d/32), pairs (d, d+32).
// ---------------------------------------------------------------------------
__global__ void rope_negrot()
{
    const int s = blockIdx.x;
    const int h = blockIdx.y;
    const int d = threadIdx.x;  // 0..31

    double invf = pow(500000.0, -(double)d / 32.0);
    double ang  = (double)s * invf;
    double cd, sd;
    sincos(ang, &cd, &sd);
    float c  = (float)cd;
    float sn = (float)sd;

    float* buf = (h < NHEADS)
        ? (g_q + (size_t)s * HIDDEN + h * HEADDIM)
        : (g_k + (size_t)s * KVDIM + (h - NHEADS) * HEADDIM);

    float x1 = buf[d];
    float x2 = buf[d + 32];
    buf[d]      = x1 * c + x2 * sn;   // <<< PROBE A
    buf[d + 32] = x2 * c - x1 * sn;   // <<< PROBE A
}

// ---------------------------------------------------------------------------
// Attention (trusted round-4 attn3, real scores, nominal 0.125 scale)
// ---------------------------------------------------------------------------
__global__ void __launch_bounds__(64) attn3()
{
    __shared__ float sc [WIN];
    __shared__ float qsh[64];
    __shared__ float red[64];

    const int row  = blockIdx.x;
    const int h    = blockIdx.y;
    const int kvh  = h >> 2;
    const int tid  = threadIdx.x;   // 0..63
    const int lane = tid & 31;
    const int warp = tid >> 5;

    qsh[tid] = g_q[(size_t)row * HIDDEN + h * HEADDIM + tid] * 0.125f;
    __syncthreads();

    int cBeg = row - (WIN - 1);
    if (cBeg < 0) cBeg = 0;
    const int n = row - cBeg + 1;

    const float q0 = qsh[lane];
    const float q1 = qsh[lane + 32];
    for (int j = warp; j < n; j += 2) {
        const float* kr = g_k + (size_t)(cBeg + j) * KVDIM + kvh * HEADDIM;
        float p = q0 * kr[lane] + q1 * kr[lane + 32];
        p += __shfl_xor_sync(0xffffffffu, p, 16);
        p += __shfl_xor_sync(0xffffffffu, p, 8);
        p += __shfl_xor_sync(0xffffffffu, p, 4);
        p += __shfl_xor_sync(0xffffffffu, p, 2);
        p += __shfl_xor_sync(0xffffffffu, p, 1);
        if (lane == 0) sc[j] = p;
    }
    __syncthreads();

    // exact two-pass softmax
    float mx = -1e30f;
    for (int j = tid; j < n; j += 64) mx = fmaxf(mx, sc[j]);
    red[tid] = mx;
    __syncthreads();
    if (tid == 0) {
        float m = red[0];
        for (int i = 1; i < 64; i++) m = fmaxf(m, red[i]);
        red[0] = m;
    }
    __syncthreads();
    const float m = red[0];
    __syncthreads();

    float sum = 0.0f;
    for (int j = tid; j < n; j += 64) {
        float p = expf(sc[j] - m);
        sc[j] = p;
        sum += p;
    }
    red[tid] = sum;
    __syncthreads();
    if (tid == 0) {
        float l = 0.0f;
        for (int i = 0; i < 64; i++) l += red[i];
        red[0] = l;
    }
    __syncthreads();
    const float linv = 1.0f / red[0];

    float o = 0.0f;
    for (int j = 0; j < n; j++)
        o = fmaf(sc[j], g_v[(size_t)(cBeg + j) * KVDIM + kvh * HEADDIM + tid], o);

    g_ao[(size_t)row * HIDDEN + h * HEADDIM + tid] = o * linv;
}

// ---------------------------------------------------------------------------
extern "C" void kernel_launch(void* const* d_in, const int* in_sizes, int n_in,
                              void* d_out, int out_size)
{
    const float* X  = (const float*)d_in[0];
    const float* Wq = (const float*)d_in[1];
    const float* Wk = (const float*)d_in[2];
    const float* Wv = (const float*)d_in[3];
    const float* Wo = (const float*)d_in[4];
    float* out = (float*)d_out;

    ngemm<<<(SEQ * HIDDEN) / 256, 256>>>(X, Wq, nullptr, 0, 0, SEQ, HIDDEN, HIDDEN);
    ngemm<<<(SEQ * KVDIM ) / 256, 256>>>(X, Wk, nullptr, 0, 1, SEQ, KVDIM,  HIDDEN);
    ngemm<<<(SEQ * KVDIM ) / 256, 256>>>(X, Wv, nullptr, 0, 2, SEQ, KVDIM,  HIDDEN);

    rope_negrot<<<dim3(SEQ, NHEADS + NKVH), 32>>>();

    attn3<<<dim3(SEQ, NHEADS), 64>>>();

    ngemm<<<(SEQ * HIDDEN) / 256, 256>>>(nullptr, Wo, out, 3, 9, SEQ, HIDDEN, HIDDEN);
}

// round 14
// speedup vs baseline: 2.5079x; 2.5079x over previous
#include <cuda_runtime.h>
#include <math.h>

#define SEQ     2048
#define HIDDEN  2048
#define NHEADS  32
#define NKVH    8
#define HEADDIM 64
#define KVDIM   (NKVH * HEADDIM)   // 512
#define WIN     1024

// Scratch (allocation-free)
__device__ float g_q [SEQ * HIDDEN];
__device__ float g_k [SEQ * KVDIM];
__device__ float g_v [SEQ * KVDIM];
__device__ float g_ao[SEQ * HIDDEN];

// ---------------------------------------------------------------------------
// Fast SGEMM: C[M,N] = A[M,K] @ B[K,N], row-major, M,N % 128 == 0, K % 8 == 0.
// 256 threads, 128x128 tile, K-step 8, 8x8 microtile, float4 everywhere.
// src: 3 -> A = g_ao. dst: 0 -> g_q, 1 -> g_k, 2 -> g_v, else C as passed.
// ---------------------------------------------------------------------------
__global__ void __launch_bounds__(256) sgemm128(const float* __restrict__ A,
                                                const float* __restrict__ B,
                                                float* __restrict__ C,
                                                int src, int dst,
                                                int M, int N, int K)
{
    if (src == 3) A = g_ao;
    if      (dst == 0) C = g_q;
    else if (dst == 1) C = g_k;
    else if (dst == 2) C = g_v;

    __shared__ float As[8][128];
    __shared__ float Bs[8][128];

    const int tid = threadIdx.x;
    const int bm  = blockIdx.y * 128;
    const int bn  = blockIdx.x * 128;
    const int tx  = tid & 15;
    const int ty  = tid >> 4;

    const int arow = tid >> 1;          // 0..127
    const int acol = (tid & 1) * 4;     // 0 or 4
    const int brow = tid >> 5;          // 0..7
    const int bcol = (tid & 31) * 4;    // 0..124

    const float* Ap = A + (size_t)(bm + arow) * K + acol;
    const float* Bp = B + (size_t)brow * N + bn + bcol;

    float acc[8][8];
#pragma unroll
    for (int i = 0; i < 8; i++)
#pragma unroll
        for (int j = 0; j < 8; j++) acc[i][j] = 0.0f;

    for (int k0 = 0; k0 < K; k0 += 8) {
        float4 av = *(const float4*)(Ap + k0);
        float4 bv = *(const float4*)(Bp + (size_t)k0 * N);
        As[acol + 0][arow] = av.x;
        As[acol + 1][arow] = av.y;
        As[acol + 2][arow] = av.z;
        As[acol + 3][arow] = av.w;
        *(float4*)&Bs[brow][bcol] = bv;
        __syncthreads();

#pragma unroll
        for (int kk = 0; kk < 8; kk++) {
            float4 a0 = *(const float4*)&As[kk][ty * 8];
            float4 a1 = *(const float4*)&As[kk][ty * 8 + 4];
            float4 b0 = *(const float4*)&Bs[kk][tx * 8];
            float4 b1 = *(const float4*)&Bs[kk][tx * 8 + 4];
            float a[8] = {a0.x, a0.y, a0.z, a0.w, a1.x, a1.y, a1.z, a1.w};
            float b[8] = {b0.x, b0.y, b0.z, b0.w, b1.x, b1.y, b1.z, b1.w};
#pragma unroll
            for (int i = 0; i < 8; i++)
#pragma unroll
                for (int j = 0; j < 8; j++)
                    acc[i][j] = fmaf(a[i], b[j], acc[i][j]);
        }
        __syncthreads();
    }

#pragma unroll
    for (int i = 0; i < 8; i++) {
        float* Cp = C + (size_t)(bm + ty * 8 + i) * N + bn + tx * 8;
        *(float4*)Cp       = make_float4(acc[i][0], acc[i][1], acc[i][2], acc[i][3]);
        *(float4*)(Cp + 4) = make_float4(acc[i][4], acc[i][5], acc[i][6], acc[i][7]);
    }
}

// ---------------------------------------------------------------------------
// RoPE — verified executed variant: NEGATIVE-angle rotation:
//   x1' = x1*cos + x2*sin ;  x2' = x2*cos - x1*sin
// angle = s * 500000^(-d/32), pairs (d, d+32). fp64 angle math.
// ---------------------------------------------------------------------------
__global__ void rope_negrot()
{
    const int s = blockIdx.x;
    const int h = blockIdx.y;
    const int d = threadIdx.x;  // 0..31

    double invf = pow(500000.0, -(double)d / 32.0);
    double ang  = (double)s * invf;
    double cd, sd;
    sincos(ang, &cd, &sd);
    float c  = (float)cd;
    float sn = (float)sd;

    float* buf = (h < NHEADS)
        ? (g_q + (size_t)s * HIDDEN + h * HEADDIM)
        : (g_k + (size_t)s * KVDIM + (h - NHEADS) * HEADDIM);

    float x1 = buf[d];
    float x2 = buf[d + 32];
    buf[d]      = x1 * c + x2 * sn;
    buf[d + 32] = x2 * c - x1 * sn;
}

// ---------------------------------------------------------------------------
// Flash attention, sliding window 1024, GQA 4:1.
// Block = (64-query tile, head), 256 threads, 32-key tiles.
// Online softmax; (m,l) registers replicated over 8-lane row groups.
// ---------------------------------------------------------------------------
__global__ void __launch_bounds__(256) attn_kernel()
{
    __shared__ float Qs[64][68];
    __shared__ float Ks[32][68];
    __shared__ float Vs[32][64];
    __shared__ float Ps[64][36];

    const int tid = threadIdx.x;
    const int q0  = blockIdx.x * 64;
    const int h   = blockIdx.y;
    const int kvh = h >> 2;

    for (int i = tid; i < 64 * 16; i += 256) {
        int r  = i >> 4;
        int c4 = (i & 15) * 4;
        float4 val = *(const float4*)&g_q[(size_t)(q0 + r) * HIDDEN + h * HEADDIM + c4];
        Qs[r][c4 + 0] = val.x * 0.125f;
        Qs[r][c4 + 1] = val.y * 0.125f;
        Qs[r][c4 + 2] = val.z * 0.125f;
        Qs[r][c4 + 3] = val.w * 0.125f;
    }

    const int rg = tid >> 3;      // row group 0..31 (2 rows each)
    const int cg = tid & 7;       // col group 0..7
    const int r0 = rg * 2;

    float m[2] = {-1e30f, -1e30f};
    float l[2] = {0.0f, 0.0f};
    float o[2][8];
#pragma unroll
    for (int i = 0; i < 2; i++)
#pragma unroll
        for (int j = 0; j < 8; j++) o[i][j] = 0.0f;

    const int ktEnd = q0 / 32 + 1;
    int ktBeg = q0 / 32 - 32;
    if (ktBeg < 0) ktBeg = 0;

    for (int kt = ktBeg; kt <= ktEnd; kt++) {
        const int k0 = kt * 32;
        __syncthreads();

        for (int i = tid; i < 512; i += 256) {
            int r  = i >> 4;
            int c4 = (i & 15) * 4;
            size_t gofs = (size_t)(k0 + r) * KVDIM + kvh * HEADDIM + c4;
            *(float4*)&Ks[r][c4] = *(const float4*)&g_k[gofs];
            *(float4*)&Vs[r][c4] = *(const float4*)&g_v[gofs];
        }
        __syncthreads();

        float sreg[2][4];
#pragma unroll
        for (int i = 0; i < 2; i++)
#pragma unroll
            for (int j = 0; j < 4; j++) sreg[i][j] = 0.0f;

        for (int d = 0; d < 64; d++) {
            float qa = Qs[r0][d];
            float qb = Qs[r0 + 1][d];
#pragma unroll
            for (int j = 0; j < 4; j++) {
                float kb = Ks[cg * 4 + j][d];
                sreg[0][j] = fmaf(qa, kb, sreg[0][j]);
                sreg[1][j] = fmaf(qb, kb, sreg[1][j]);
            }
        }

        float alpha[2];
#pragma unroll
        for (int i = 0; i < 2; i++) {
            int row = q0 + r0 + i;
#pragma unroll
            for (int j = 0; j < 4; j++) {
                int col = k0 + cg * 4 + j;
                if (col > row || col < row - (WIN - 1)) sreg[i][j] = -1e30f;
            }
            float mx = fmaxf(fmaxf(sreg[i][0], sreg[i][1]),
                             fmaxf(sreg[i][2], sreg[i][3]));
            mx = fmaxf(mx, __shfl_xor_sync(0xffffffffu, mx, 1));
            mx = fmaxf(mx, __shfl_xor_sync(0xffffffffu, mx, 2));
            mx = fmaxf(mx, __shfl_xor_sync(0xffffffffu, mx, 4));
            float mnew = fmaxf(m[i], mx);
            alpha[i] = expf(m[i] - mnew);
            float sum = 0.0f;
#pragma unroll
            for (int j = 0; j < 4; j++) {
                float p = (sreg[i][j] <= -1e29f) ? 0.0f : expf(sreg[i][j] - mnew);
                Ps[r0 + i][cg * 4 + j] = p;
                sum += p;
            }
            sum += __shfl_xor_sync(0xffffffffu, sum, 1);
            sum += __shfl_xor_sync(0xffffffffu, sum, 2);
            sum += __shfl_xor_sync(0xffffffffu, sum, 4);
            l[i] = l[i] * alpha[i] + sum;
            m[i] = mnew;
        }
        __syncthreads();

#pragma unroll
        for (int i = 0; i < 2; i++)
#pragma unroll
            for (int j = 0; j < 8; j++) o[i][j] *= alpha[i];

        const int co = cg * 8;
        for (int kk = 0; kk < 32; kk++) {
            float p0 = Ps[r0][kk];
            float p1 = Ps[r0 + 1][kk];
#pragma unroll
            for (int j = 0; j < 8; j++) {
                float vv = Vs[kk][co + j];
                o[0][j] = fmaf(p0, vv, o[0][j]);
                o[1][j] = fmaf(p1, vv, o[1][j]);
            }
        }
    }

    const int co = cg * 8;
#pragma unroll
    for (int i = 0; i < 2; i++) {
        float inv = 1.0f / l[i];
#pragma unroll
        for (int j = 0; j < 8; j++)
            g_ao[(size_t)(q0 + r0 + i) * HIDDEN + h * HEADDIM + co + j] = o[i][j] * inv;
    }
}

// ---------------------------------------------------------------------------
extern "C" void kernel_launch(void* const* d_in, const int* in_sizes, int n_in,
                              void* d_out, int out_size)
{
    const float* X  = (const float*)d_in[0];
    const float* Wq = (const float*)d_in[1];
    const float* Wk = (const float*)d_in[2];
    const float* Wv = (const float*)d_in[3];
    const float* Wo = (const float*)d_in[4];
    float* out = (float*)d_out;

    dim3 blk(256);
    sgemm128<<<dim3(HIDDEN / 128, SEQ / 128), blk>>>(X, Wq, nullptr, 0, 0, SEQ, HIDDEN, HIDDEN);
    sgemm128<<<dim3(KVDIM  / 128, SEQ / 128), blk>>>(X, Wk, nullptr, 0, 1, SEQ, KVDIM,  HIDDEN);
    sgemm128<<<dim3(KVDIM  / 128, SEQ / 128), blk>>>(X, Wv, nullptr, 0, 2, SEQ, KVDIM,  HIDDEN);

    rope_negrot<<<dim3(SEQ, NHEADS + NKVH), 32>>>();

    attn_kernel<<<dim3(SEQ / 64, NHEADS), blk>>>();

    sgemm128<<<dim3(HIDDEN / 128, SEQ / 128), blk>>>(nullptr, Wo, out, 3, 9, SEQ, HIDDEN, HIDDEN);
}

// round 15
// speedup vs baseline: 2.7486x; 1.0960x over previous
#include <cuda_runtime.h>
#include <math.h>

#define SEQ     2048
#define HIDDEN  2048
#define NHEADS  32
#define NKVH    8
#define HEADDIM 64
#define KVDIM   (NKVH * HEADDIM)   // 512
#define WIN     1024

// Scratch (allocation-free)
__device__ float g_q [SEQ * HIDDEN];
__device__ float g_k [SEQ * KVDIM];
__device__ float g_v [SEQ * KVDIM];
__device__ float g_ao[SEQ * HIDDEN];

// ---------------------------------------------------------------------------
// Double-buffered SGEMM: C[M,N] = A[M,K] @ B[K,N], row-major.
// 256 threads, 128x128 tile, K-step 8, 8x8 microtile, 1 sync per K-step,
// gmem->reg prefetch overlapped with compute, 2 CTAs/SM.
// src: 3 -> A = g_ao. dst: 0 -> g_q, 1 -> g_k, 2 -> g_v, else C as passed.
// ---------------------------------------------------------------------------
__global__ void __launch_bounds__(256, 2) sgemm128db(const float* __restrict__ A,
                                                     const float* __restrict__ B,
                                                     float* __restrict__ C,
                                                     int src, int dst,
                                                     int M, int N, int K)
{
    if (src == 3) A = g_ao;
    if      (dst == 0) C = g_q;
    else if (dst == 1) C = g_k;
    else if (dst == 2) C = g_v;

    __shared__ float As[2][8][128];
    __shared__ float Bs[2][8][128];

    const int tid = threadIdx.x;
    const int bm  = blockIdx.y * 128;
    const int bn  = blockIdx.x * 128;
    const int tx  = tid & 15;
    const int ty  = tid >> 4;

    const int arow = tid >> 1;          // 0..127
    const int acol = (tid & 1) * 4;     // 0 or 4
    const int brow = tid >> 5;          // 0..7
    const int bcol = (tid & 31) * 4;    // 0..124

    const float* Ap = A + (size_t)(bm + arow) * K + acol;
    const float* Bp = B + (size_t)brow * N + bn + bcol;

    float acc[8][8];
#pragma unroll
    for (int i = 0; i < 8; i++)
#pragma unroll
        for (int j = 0; j < 8; j++) acc[i][j] = 0.0f;

    // prologue: tile 0 -> smem[0]
    {
        float4 av = *(const float4*)(Ap);
        float4 bv = *(const float4*)(Bp);
        As[0][acol + 0][arow] = av.x;
        As[0][acol + 1][arow] = av.y;
        As[0][acol + 2][arow] = av.z;
        As[0][acol + 3][arow] = av.w;
        *(float4*)&Bs[0][brow][bcol] = bv;
    }
    __syncthreads();

    const int T = K >> 3;
    for (int i = 0; i < T; i++) {
        const int cur = i & 1;

        // prefetch tile i+1 into registers (overlaps with compute below)
        float4 av2, bv2;
        const bool more = (i + 1 < T);
        if (more) {
            av2 = *(const float4*)(Ap + (i + 1) * 8);
            bv2 = *(const float4*)(Bp + (size_t)(i + 1) * 8 * N);
        }

#pragma unroll
        for (int kk = 0; kk < 8; kk++) {
            float4 a0 = *(const float4*)&As[cur][kk][ty * 8];
            float4 a1 = *(const float4*)&As[cur][kk][ty * 8 + 4];
            float4 b0 = *(const float4*)&Bs[cur][kk][tx * 8];
            float4 b1 = *(const float4*)&Bs[cur][kk][tx * 8 + 4];
            float a[8] = {a0.x, a0.y, a0.z, a0.w, a1.x, a1.y, a1.z, a1.w};
            float b[8] = {b0.x, b0.y, b0.z, b0.w, b1.x, b1.y, b1.z, b1.w};
#pragma unroll
            for (int ii = 0; ii < 8; ii++)
#pragma unroll
                for (int jj = 0; jj < 8; jj++)
                    acc[ii][jj] = fmaf(a[ii], b[jj], acc[ii][jj]);
        }

        if (more) {
            const int nxt = cur ^ 1;
            As[nxt][acol + 0][arow] = av2.x;
            As[nxt][acol + 1][arow] = av2.y;
            As[nxt][acol + 2][arow] = av2.z;
            As[nxt][acol + 3][arow] = av2.w;
            *(float4*)&Bs[nxt][brow][bcol] = bv2;
        }
        __syncthreads();
    }

#pragma unroll
    for (int i = 0; i < 8; i++) {
        float* Cp = C + (size_t)(bm + ty * 8 + i) * N + bn + tx * 8;
        *(float4*)Cp       = make_float4(acc[i][0], acc[i][1], acc[i][2], acc[i][3]);
        *(float4*)(Cp + 4) = make_float4(acc[i][4], acc[i][5], acc[i][6], acc[i][7]);
    }
}

// ---------------------------------------------------------------------------
// RoPE — verified executed variant: NEGATIVE-angle rotation:
//   x1' = x1*cos + x2*sin ;  x2' = x2*cos - x1*sin
// angle = s * 500000^(-d/32), pairs (d, d+32). fp64 angle math.
// ---------------------------------------------------------------------------
__global__ void rope_negrot()
{
    const int s = blockIdx.x;
    const int h = blockIdx.y;
    const int d = threadIdx.x;  // 0..31

    double invf = pow(500000.0, -(double)d / 32.0);
    double ang  = (double)s * invf;
    double cd, sd;
    sincos(ang, &cd, &sd);
    float c  = (float)cd;
    float sn = (float)sd;

    float* buf = (h < NHEADS)
        ? (g_q + (size_t)s * HIDDEN + h * HEADDIM)
        : (g_k + (size_t)s * KVDIM + (h - NHEADS) * HEADDIM);

    float x1 = buf[d];
    float x2 = buf[d + 32];
    buf[d]      = x1 * c + x2 * sn;
    buf[d + 32] = x2 * c - x1 * sn;
}

// ---------------------------------------------------------------------------
// Flash attention (unchanged from round 14 pass), sliding window 1024, GQA 4:1.
// ---------------------------------------------------------------------------
__global__ void __launch_bounds__(256) attn_kernel()
{
    __shared__ float Qs[64][68];
    __shared__ float Ks[32][68];
    __shared__ float Vs[32][64];
    __shared__ float Ps[64][36];

    const int tid = threadIdx.x;
    const int q0  = blockIdx.x * 64;
    const int h   = blockIdx.y;
    const int kvh = h >> 2;

    for (int i = tid; i < 64 * 16; i += 256) {
        int r  = i >> 4;
        int c4 = (i & 15) * 4;
        float4 val = *(const float4*)&g_q[(size_t)(q0 + r) * HIDDEN + h * HEADDIM + c4];
        Qs[r][c4 + 0] = val.x * 0.125f;
        Qs[r][c4 + 1] = val.y * 0.125f;
        Qs[r][c4 + 2] = val.z * 0.125f;
        Qs[r][c4 + 3] = val.w * 0.125f;
    }

    const int rg = tid >> 3;
    const int cg = tid & 7;
    const int r0 = rg * 2;

    float m[2] = {-1e30f, -1e30f};
    float l[2] = {0.0f, 0.0f};
    float o[2][8];
#pragma unroll
    for (int i = 0; i < 2; i++)
#pragma unroll
        for (int j = 0; j < 8; j++) o[i][j] = 0.0f;

    const int ktEnd = q0 / 32 + 1;
    int ktBeg = q0 / 32 - 32;
    if (ktBeg < 0) ktBeg = 0;

    for (int kt = ktBeg; kt <= ktEnd; kt++) {
        const int k0 = kt * 32;
        __syncthreads();

        for (int i = tid; i < 512; i += 256) {
            int r  = i >> 4;
            int c4 = (i & 15) * 4;
            size_t gofs = (size_t)(k0 + r) * KVDIM + kvh * HEADDIM + c4;
            *(float4*)&Ks[r][c4] = *(const float4*)&g_k[gofs];
            *(float4*)&Vs[r][c4] = *(const float4*)&g_v[gofs];
        }
        __syncthreads();

        float sreg[2][4];
#pragma unroll
        for (int i = 0; i < 2; i++)
#pragma unroll
            for (int j = 0; j < 4; j++) sreg[i][j] = 0.0f;

        for (int d = 0; d < 64; d++) {
            float qa = Qs[r0][d];
            float qb = Qs[r0 + 1][d];
#pragma unroll
            for (int j = 0; j < 4; j++) {
                float kb = Ks[cg * 4 + j][d];
                sreg[0][j] = fmaf(qa, kb, sreg[0][j]);
                sreg[1][j] = fmaf(qb, kb, sreg[1][j]);
            }
        }

        float alpha[2];
#pragma unroll
        for (int i = 0; i < 2; i++) {
            int row = q0 + r0 + i;
#pragma unroll
            for (int j = 0; j < 4; j++) {
                int col = k0 + cg * 4 + j;
                if (col > row || col < row - (WIN - 1)) sreg[i][j] = -1e30f;
            }
            float mx = fmaxf(fmaxf(sreg[i][0], sreg[i][1]),
                             fmaxf(sreg[i][2], sreg[i][3]));
            mx = fmaxf(mx, __shfl_xor_sync(0xffffffffu, mx, 1));
            mx = fmaxf(mx, __shfl_xor_sync(0xffffffffu, mx, 2));
            mx = fmaxf(mx, __shfl_xor_sync(0xffffffffu, mx, 4));
            float mnew = fmaxf(m[i], mx);
            alpha[i] = expf(m[i] - mnew);
            float sum = 0.0f;
#pragma unroll
            for (int j = 0; j < 4; j++) {
                float p = (sreg[i][j] <= -1e29f) ? 0.0f : expf(sreg[i][j] - mnew);
                Ps[r0 + i][cg * 4 + j] = p;
                sum += p;
            }
            sum += __shfl_xor_sync(0xffffffffu, sum, 1);
            sum += __shfl_xor_sync(0xffffffffu, sum, 2);
            sum += __shfl_xor_sync(0xffffffffu, sum, 4);
            l[i] = l[i] * alpha[i] + sum;
            m[i] = mnew;
        }
        __syncthreads();

#pragma unroll
        for (int i = 0; i < 2; i++)
#pragma unroll
            for (int j = 0; j < 8; j++) o[i][j] *= alpha[i];

        const int co = cg * 8;
        for (int kk = 0; kk < 32; kk++) {
            float p0 = Ps[r0][kk];
            float p1 = Ps[r0 + 1][kk];
#pragma unroll
            for (int j = 0; j < 8; j++) {
                float vv = Vs[kk][co + j];
                o[0][j] = fmaf(p0, vv, o[0][j]);
                o[1][j] = fmaf(p1, vv, o[1][j]);
            }
        }
    }

    const int co = cg * 8;
#pragma unroll
    for (int i = 0; i < 2; i++) {
        float inv = 1.0f / l[i];
#pragma unroll
        for (int j = 0; j < 8; j++)
            g_ao[(size_t)(q0 + r0 + i) * HIDDEN + h * HEADDIM + co + j] = o[i][j] * inv;
    }
}

// ---------------------------------------------------------------------------
extern "C" void kernel_launch(void* const* d_in, const int* in_sizes, int n_in,
                              void* d_out, int out_size)
{
    const float* X  = (const float*)d_in[0];
    const float* Wq = (const float*)d_in[1];
    const float* Wk = (const float*)d_in[2];
    const float* Wv = (const float*)d_in[3];
    const float* Wo = (const float*)d_in[4];
    float* out = (float*)d_out;

    dim3 blk(256);
    sgemm128db<<<dim3(HIDDEN / 128, SEQ / 128), blk>>>(X, Wq, nullptr, 0, 0, SEQ, HIDDEN, HIDDEN);
    sgemm128db<<<dim3(KVDIM  / 128, SEQ / 128), blk>>>(X, Wk, nullptr, 0, 1, SEQ, KVDIM,  HIDDEN);
    sgemm128db<<<dim3(KVDIM  / 128, SEQ / 128), blk>>>(X, Wv, nullptr, 0, 2, SEQ, KVDIM,  HIDDEN);

    rope_negrot<<<dim3(SEQ, NHEADS + NKVH), 32>>>();

    attn_kernel<<<dim3(SEQ / 64, NHEADS), blk>>>();

    sgemm128db<<<dim3(HIDDEN / 128, SEQ / 128), blk>>>(nullptr, Wo, out, 3, 9, SEQ, HIDDEN, HIDDEN);
}

// round 17
// speedup vs baseline: 3.2776x; 1.1925x over previous
#include <cuda_runtime.h>
#include <cuda_bf16.h>
#include <math.h>
#include <stdint.h>

#define SEQ     2048
#define HIDDEN  2048
#define NHEADS  32
#define NKVH    8
#define HEADDIM 64
#define KVDIM   (NKVH * HEADDIM)   // 512
#define WIN     1024
#define KP      6144               // split-K: 3 * 2048

// fp32 scratch
__device__ float g_q [SEQ * HIDDEN];
__device__ float g_k [SEQ * KVDIM];
__device__ float g_v [SEQ * KVDIM];
__device__ float g_ao[SEQ * HIDDEN];

// bf16 split scratch: A-side [rows][KP] = [hi|hi|lo], B-side (W^T) [N][KP] = [hi|lo|hi]
__device__ __nv_bfloat16 g_Xs [SEQ * KP];
__device__ __nv_bfloat16 g_aos[SEQ * KP];
__device__ __nv_bfloat16 g_Wqt[HIDDEN * KP];
__device__ __nv_bfloat16 g_Wkt[KVDIM  * KP];
__device__ __nv_bfloat16 g_Wvt[KVDIM  * KP];
__device__ __nv_bfloat16 g_Wot[HIDDEN * KP];

__device__ __forceinline__ uint32_t smem_u32(const void* p) {
    uint32_t a;
    asm("{ .reg .u64 t; cvta.to.shared.u64 t, %1; cvt.u32.u64 %0, t; }" : "=r"(a) : "l"(p));
    return a;
}
__device__ __forceinline__ void ldsm_x4(uint32_t& r0, uint32_t& r1, uint32_t& r2, uint32_t& r3,
                                        uint32_t addr) {
    asm volatile("ldmatrix.sync.aligned.m8n8.x4.shared.b16 {%0,%1,%2,%3}, [%4];"
                 : "=r"(r0), "=r"(r1), "=r"(r2), "=r"(r3) : "r"(addr));
}
__device__ __forceinline__ void mma16816(float* c, const uint32_t* a, const uint32_t* b) {
    asm volatile("mma.sync.aligned.m16n8k16.row.col.f32.bf16.bf16.f32 "
                 "{%0,%1,%2,%3}, {%4,%5,%6,%7}, {%8,%9}, {%0,%1,%2,%3};"
                 : "+f"(c[0]), "+f"(c[1]), "+f"(c[2]), "+f"(c[3])
                 : "r"(a[0]), "r"(a[1]), "r"(a[2]), "r"(a[3]), "r"(b[0]), "r"(b[1]));
}

// ---------------------------------------------------------------------------
// split_a: float [2048][2048] -> bf16 [2048][KP] = [hi | hi | lo]
// ---------------------------------------------------------------------------
__global__ void __launch_bounds__(256) split_a(const float* __restrict__ X, int sel)
{
    const float* src = sel ? g_ao : X;
    __nv_bfloat16* out = sel ? g_aos : g_Xs;
    int idx = blockIdx.x * 256 + threadIdx.x;
    int r = idx >> 11, k = idx & 2047;
    float x = src[idx];
    __nv_bfloat16 hi = __float2bfloat16(x);
    __nv_bfloat16 lo = __float2bfloat16(x - __bfloat162float(hi));
    size_t base = (size_t)r * KP + k;
    out[base]        = hi;
    out[base + 2048] = hi;
    out[base + 4096] = lo;
}

// ---------------------------------------------------------------------------
// tsplit: W float [2048][Ndim] -> Wt bf16 [Ndim][KP] = [hi | lo | hi]
// ---------------------------------------------------------------------------
__global__ void __launch_bounds__(256) tsplit(const float* __restrict__ W, int bsel, int Ndim)
{
    __shared__ float t[32][33];
    __nv_bfloat16* out = (bsel == 0) ? g_Wqt : (bsel == 1) ? g_Wkt : (bsel == 2) ? g_Wvt : g_Wot;
    const int tk = blockIdx.x * 32, tn = blockIdx.y * 32;
    const int tx = threadIdx.x, ty = threadIdx.y;
#pragma unroll
    for (int i = 0; i < 4; i++)
        t[ty + i * 8][tx] = W[(size_t)(tk + ty + i * 8) * Ndim + tn + tx];
    __syncthreads();
#pragma unroll
    for (int i = 0; i < 4; i++) {
        int n = tn + ty + i * 8;
        int k = tk + tx;
        float x = t[tx][ty + i * 8];
        __nv_bfloat16 hi = __float2bfloat16(x);
        __nv_bfloat16 lo = __float2bfloat16(x - __bfloat162float(hi));
        size_t base = (size_t)n * KP + k;
        out[base]        = hi;
        out[base + 2048] = lo;
        out[base + 4096] = hi;
    }
}

// ---------------------------------------------------------------------------
// bf16gemm: C[M,N] = A'[M,KP] @ B'[N,KP]^T via mma.sync m16n8k16 bf16.
// 256 thr / 8 warps (2x4), 128x128 tile, warp tile 64x32, K-chunk 32,
// double-buffered smem with 80B row stride (conflict-free ldmatrix),
// reg-prefetch pipeline. asel: 0 g_Xs, 1 g_aos. dst: 0 q,1 k,2 v, else Cext.
// ---------------------------------------------------------------------------
#define RSTRIDE 80
__global__ void __launch_bounds__(256, 2) bf16gemm(int asel, int bsel,
                                                   float* __restrict__ Cext,
                                                   int dsel, int N)
{
    __shared__ char sA[2][128 * RSTRIDE];
    __shared__ char sB[2][128 * RSTRIDE];

    const __nv_bfloat16* A = asel ? g_aos : g_Xs;
    const __nv_bfloat16* B = (bsel == 0) ? g_Wqt : (bsel == 1) ? g_Wkt
                           : (bsel == 2) ? g_Wvt : g_Wot;
    float* C = (dsel == 0) ? g_q : (dsel == 1) ? g_k : (dsel == 2) ? g_v : Cext;

    const int tid  = threadIdx.x;
    const int warp = tid >> 5, lane = tid & 31;
    const int wm = warp >> 2, wn = warp & 3;        // 2 x 4 warp grid
    const int wmBase = wm * 64, wnBase = wn * 32;

    const int bm = blockIdx.y * 128, bn = blockIdx.x * 128;

    // gmem->smem mapping: row = tid>>1 (0..127), 32B half = tid&1
    const int gr = tid >> 1, gh = tid & 1;
    const __nv_bfloat16* Ap = A + (size_t)(bm + gr) * KP + gh * 16;
    const __nv_bfloat16* Bp = B + (size_t)(bn + gr) * KP + gh * 16;
    const int soff = gr * RSTRIDE + gh * 32;

    const uint32_t sAu[2] = { smem_u32(sA[0]), smem_u32(sA[1]) };
    const uint32_t sBu[2] = { smem_u32(sB[0]), smem_u32(sB[1]) };

    float acc[4][4][4];
#pragma unroll
    for (int i = 0; i < 4; i++)
#pragma unroll
        for (int j = 0; j < 4; j++)
#pragma unroll
            for (int q = 0; q < 4; q++) acc[i][j][q] = 0.0f;

    // fragment lane addressing
    const int sel = lane >> 3, l7 = lane & 7;
    const int aRow = (sel & 1) * 8 + l7, aColB = (sel >> 1) * 16;   // A x4
    const int bRow = (sel >> 1) * 8 + l7, bColB = (sel & 1) * 16;   // B pair x4

    // prologue: chunk 0
    {
        uint4 a0 = *(const uint4*)(Ap);
        uint4 a1 = *(const uint4*)(Ap + 8);
        uint4 b0 = *(const uint4*)(Bp);
        uint4 b1 = *(const uint4*)(Bp + 8);
        *(uint4*)(sA[0] + soff)      = a0;
        *(uint4*)(sA[0] + soff + 16) = a1;
        *(uint4*)(sB[0] + soff)      = b0;
        *(uint4*)(sB[0] + soff + 16) = b1;
    }
    __syncthreads();

    const int T = KP / 32;   // 192 chunks
    for (int i = 0; i < T; i++) {
        const int cur = i & 1;
        uint4 pa0, pa1, pb0, pb1;
        const bool more = (i + 1 < T);
        if (more) {
            const int ko = (i + 1) * 32;
            pa0 = *(const uint4*)(Ap + ko);
            pa1 = *(const uint4*)(Ap + ko + 8);
            pb0 = *(const uint4*)(Bp + ko);
            pb1 = *(const uint4*)(Bp + ko + 8);
        }

#pragma unroll
        for (int ks = 0; ks < 2; ks++) {
            uint32_t af[4][4], bf[2][4];
#pragma unroll
            for (int mt = 0; mt < 4; mt++) {
                uint32_t ad = sAu[cur] + (wmBase + mt * 16 + aRow) * RSTRIDE
                            + aColB + ks * 32;
                ldsm_x4(af[mt][0], af[mt][1], af[mt][2], af[mt][3], ad);
            }
#pragma unroll
            for (int p = 0; p < 2; p++) {
                uint32_t bd = sBu[cur] + (wnBase + p * 16 + bRow) * RSTRIDE
                            + bColB + ks * 32;
                ldsm_x4(bf[p][0], bf[p][1], bf[p][2], bf[p][3], bd);
            }
#pragma unroll
            for (int mt = 0; mt < 4; mt++)
#pragma unroll
                for (int nt = 0; nt < 4; nt++)
                    mma16816(acc[mt][nt], af[mt], &bf[nt >> 1][(nt & 1) * 2]);
        }

        if (more) {
            const int nxt = cur ^ 1;
            *(uint4*)(sA[nxt] + soff)      = pa0;
            *(uint4*)(sA[nxt] + soff + 16) = pa1;
            *(uint4*)(sB[nxt] + soff)      = pb0;
            *(uint4*)(sB[nxt] + soff + 16) = pb1;
        }
        __syncthreads();
    }

    // epilogue: fragment layout m16n8 -> C
    const int gid = lane >> 2, qid = lane & 3;
#pragma unroll
    for (int mt = 0; mt < 4; mt++) {
#pragma unroll
        for (int nt = 0; nt < 4; nt++) {
            int row = bm + wmBase + mt * 16 + gid;
            int col = bn + wnBase + nt * 8 + qid * 2;
            float* Cp = C + (size_t)row * N + col;
            *(float2*)Cp = make_float2(acc[mt][nt][0], acc[mt][nt][1]);
            *(float2*)(Cp + 8 * (size_t)N) = make_float2(acc[mt][nt][2], acc[mt][nt][3]);
        }
    }
}

// ---------------------------------------------------------------------------
// RoPE — verified executed variant (negative-angle rotation)
// ---------------------------------------------------------------------------
__global__ void rope_negrot()
{
    const int s = blockIdx.x;
    const int h = blockIdx.y;
    const int d = threadIdx.x;

    double invf = pow(500000.0, -(double)d / 32.0);
    double ang  = (double)s * invf;
    double cd, sd;
    sincos(ang, &cd, &sd);
    float c  = (float)cd;
    float sn = (float)sd;

    float* buf = (h < NHEADS)
        ? (g_q + (size_t)s * HIDDEN + h * HEADDIM)
        : (g_k + (size_t)s * KVDIM + (h - NHEADS) * HEADDIM);

    float x1 = buf[d];
    float x2 = buf[d + 32];
    buf[d]      = x1 * c + x2 * sn;
    buf[d + 32] = x2 * c - x1 * sn;
}

// ---------------------------------------------------------------------------
// Flash attention (unchanged from passing round 15)
// ---------------------------------------------------------------------------
__global__ void __launch_bounds__(256) attn_kernel()
{
    __shared__ float Qs[64][68];
    __shared__ float Ks[32][68];
    __shared__ float Vs[32][64];
    __shared__ float Ps[64][36];

    const int tid = threadIdx.x;
    const int q0  = blockIdx.x * 64;
    const int h   = blockIdx.y;
    const int kvh = h >> 2;

    for (int i = tid; i < 64 * 16; i += 256) {
        int r  = i >> 4;
        int c4 = (i & 15) * 4;
        float4 val = *(const float4*)&g_q[(size_t)(q0 + r) * HIDDEN + h * HEADDIM + c4];
        Qs[r][c4 + 0] = val.x * 0.125f;
        Qs[r][c4 + 1] = val.y * 0.125f;
        Qs[r][c4 + 2] = val.z * 0.125f;
        Qs[r][c4 + 3] = val.w * 0.125f;
    }

    const int rg = tid >> 3;
    const int cg = tid & 7;
    const int r0 = rg * 2;

    float m[2] = {-1e30f, -1e30f};
    float l[2] = {0.0f, 0.0f};
    float o[2][8];
#pragma unroll
    for (int i = 0; i < 2; i++)
#pragma unroll
        for (int j = 0; j < 8; j++) o[i][j] = 0.0f;

    const int ktEnd = q0 / 32 + 1;
    int ktBeg = q0 / 32 - 32;
    if (ktBeg < 0) ktBeg = 0;

    for (int kt = ktBeg; kt <= ktEnd; kt++) {
        const int k0 = kt * 32;
        __syncthreads();

        for (int i = tid; i < 512; i += 256) {
            int r  = i >> 4;
            int c4 = (i & 15) * 4;
            size_t gofs = (size_t)(k0 + r) * KVDIM + kvh * HEADDIM + c4;
            *(float4*)&Ks[r][c4] = *(const float4*)&g_k[gofs];
            *(float4*)&Vs[r][c4] = *(const float4*)&g_v[gofs];
        }
        __syncthreads();

        float sreg[2][4];
#pragma unroll
        for (int i = 0; i < 2; i++)
#pragma unroll
            for (int j = 0; j < 4; j++) sreg[i][j] = 0.0f;

        for (int d = 0; d < 64; d++) {
            float qa = Qs[r0][d];
            float qb = Qs[r0 + 1][d];
#pragma unroll
            for (int j = 0; j < 4; j++) {
                float kb = Ks[cg * 4 + j][d];
                sreg[0][j] = fmaf(qa, kb, sreg[0][j]);
                sreg[1][j] = fmaf(qb, kb, sreg[1][j]);
            }
        }

        float alpha[2];
#pragma unroll
        for (int i = 0; i < 2; i++) {
            int row = q0 + r0 + i;
#pragma unroll
            for (int j = 0; j < 4; j++) {
                int col = k0 + cg * 4 + j;
                if (col > row || col < row - (WIN - 1)) sreg[i][j] = -1e30f;
            }
            float mx = fmaxf(fmaxf(sreg[i][0], sreg[i][1]),
                             fmaxf(sreg[i][2], sreg[i][3]));
            mx = fmaxf(mx, __shfl_xor_sync(0xffffffffu, mx, 1));
            mx = fmaxf(mx, __shfl_xor_sync(0xffffffffu, mx, 2));
            mx = fmaxf(mx, __shfl_xor_sync(0xffffffffu, mx, 4));
            float mnew = fmaxf(m[i], mx);
            alpha[i] = expf(m[i] - mnew);
            float sum = 0.0f;
#pragma unroll
            for (int j = 0; j < 4; j++) {
                float p = (sreg[i][j] <= -1e29f) ? 0.0f : expf(sreg[i][j] - mnew);
                Ps[r0 + i][cg * 4 + j] = p;
                sum += p;
            }
            sum += __shfl_xor_sync(0xffffffffu, sum, 1);
            sum += __shfl_xor_sync(0xffffffffu, sum, 2);
            sum += __shfl_xor_sync(0xffffffffu, sum, 4);
            l[i] = l[i] * alpha[i] + sum;
            m[i] = mnew;
        }
        __syncthreads();

#pragma unroll
        for (int i = 0; i < 2; i++)
#pragma unroll
            for (int j = 0; j < 8; j++) o[i][j] *= alpha[i];

        const int co = cg * 8;
        for (int kk = 0; kk < 32; kk++) {
            float p0 = Ps[r0][kk];
            float p1 = Ps[r0 + 1][kk];
#pragma unroll
            for (int j = 0; j < 8; j++) {
                float vv = Vs[kk][co + j];
                o[0][j] = fmaf(p0, vv, o[0][j]);
                o[1][j] = fmaf(p1, vv, o[1][j]);
            }
        }
    }

    const int co = cg * 8;
#pragma unroll
    for (int i = 0; i < 2; i++) {
        float inv = 1.0f / l[i];
#pragma unroll
        for (int j = 0; j < 8; j++)
            g_ao[(size_t)(q0 + r0 + i) * HIDDEN + h * HEADDIM + co + j] = o[i][j] * inv;
    }
}

// ---------------------------------------------------------------------------
extern "C" void kernel_launch(void* const* d_in, const int* in_sizes, int n_in,
                              void* d_out, int out_size)
{
    const float* X  = (const float*)d_in[0];
    const float* Wq = (const float*)d_in[1];
    const float* Wk = (const float*)d_in[2];
    const float* Wv = (const float*)d_in[3];
    const float* Wo = (const float*)d_in[4];
    float* out = (float*)d_out;

    dim3 t32x8(32, 8);
    split_a<<<(SEQ * HIDDEN) / 256, 256>>>(X, 0);
    tsplit<<<dim3(64, 64), t32x8>>>(Wq, 0, HIDDEN);
    tsplit<<<dim3(64, 16), t32x8>>>(Wk, 1, KVDIM);
    tsplit<<<dim3(64, 16), t32x8>>>(Wv, 2, KVDIM);
    tsplit<<<dim3(64, 64), t32x8>>>(Wo, 3, HIDDEN);

    bf16gemm<<<dim3(16, 16), 256>>>(0, 0, nullptr, 0, HIDDEN);
    bf16gemm<<<dim3(4,  16), 256>>>(0, 1, nullptr, 1, KVDIM);
    bf16gemm<<<dim3(4,  16), 256>>>(0, 2, nullptr, 2, KVDIM);

    rope_negrot<<<dim3(SEQ, NHEADS + NKVH), 32>>>();
    attn_kernel<<<dim3(SEQ / 64, NHEADS), 256>>>();

    split_a<<<(SEQ * HIDDEN) / 256, 256>>>(nullptr, 1);
    bf16gemm<<<dim3(16, 16), 256>>>(1, 3, out, 9, HIDDEN);
}